// round 1
// baseline (speedup 1.0000x reference)
#include <cuda_runtime.h>
#include <cuda_bf16.h>
#include <math.h>

#define D_    1024
#define DEPTH 8
#define H_    16
#define DH_   64
#define INNER 1024
#define NQ_   8
#define ED_   768
#define FF_   4096
#define TD_   320
#define BS_   32
#define N1_   1024
#define SCALE_ 0.125f

#define ACT_NONE 0
#define ACT_SILU 1
#define ACT_GELU 2

// ---------------- static scratch (no runtime allocation allowed) ----------------
__device__ float         g_xp[BS_*N1_*D_];          // 134 MB
__device__ __nv_bfloat16 g_xnorm[BS_*N1_*D_];       // 67 MB
__device__ float g_temb0[BS_*TD_];
__device__ float g_temb1[BS_*D_];
__device__ float g_temb [BS_*D_];
__device__ float g_stemb[BS_*D_];
__device__ float g_ada  [BS_*4*D_];
__device__ float g_lat  [BS_*NQ_*D_];
__device__ float g_latn [BS_*NQ_*D_];
__device__ float g_q    [BS_*NQ_*D_];
__device__ float g_qp   [BS_*NQ_*H_*D_];            // (b,q,h,d) 16.8 MB
__device__ float g_att  [BS_*NQ_*H_*N1_];           // logits -> attn, 16.8 MB
__device__ float g_ov   [BS_*NQ_*H_*D_];            // 16.8 MB
__device__ float g_vout [BS_*NQ_*D_];
__device__ float g_hff  [BS_*NQ_*D_];
__device__ float g_h1   [BS_*NQ_*FF_];

// ---------------- generic tiled SGEMM: C = act(alpha*A(.ascale)@B(/Bt) + bias) [+C] ----
// BM=BN=64, BK=16, 256 threads, 4x4 per thread. K must be a multiple of 16 (true here).
template<typename TA, typename TB, typename TC, int ACT, bool ADD_C, bool ASCALE, bool BT>
__global__ void __launch_bounds__(256) gemm_k(
    int M, int N, int K,
    const TA* __restrict__ A, int lda, long sA,
    const TB* __restrict__ B, int ldb, long sB,
    TC* __restrict__ C, int ldc, long sC,
    const float* __restrict__ bias,
    const float* __restrict__ ascale,
    float alpha)
{
    __shared__ float As[16][68];
    __shared__ float Bs[16][68];
    A += (long)blockIdx.z * sA;
    B += (long)blockIdx.z * sB;
    C += (long)blockIdx.z * sC;
    const int bm = blockIdx.y * 64;
    const int bn = blockIdx.x * 64;
    const int tid = threadIdx.x;
    const int tx = tid & 15, ty = tid >> 4;

    float acc[4][4];
#pragma unroll
    for (int i = 0; i < 4; i++)
#pragma unroll
        for (int j = 0; j < 4; j++) acc[i][j] = 0.f;

    for (int k0 = 0; k0 < K; k0 += 16) {
#pragma unroll
        for (int i = 0; i < 4; i++) {
            int idx = tid + i * 256;
            int r = idx >> 4, kk = idx & 15;
            float v = 0.f;
            int gr = bm + r;
            if (gr < M) v = (float)A[(long)gr * lda + (k0 + kk)];
            if (ASCALE) v *= ascale[k0 + kk];
            As[kk][r] = v;
        }
#pragma unroll
        for (int i = 0; i < 4; i++) {
            int idx = tid + i * 256;
            if (!BT) {
                int kk = idx >> 6, c = idx & 63;
                int gc = bn + c;
                float v = 0.f;
                if (gc < N) v = (float)B[(long)(k0 + kk) * ldb + gc];
                Bs[kk][c] = v;
            } else {
                int c = idx >> 4, kk = idx & 15;
                int gc = bn + c;
                float v = 0.f;
                if (gc < N) v = (float)B[(long)gc * ldb + (k0 + kk)];
                Bs[kk][c] = v;
            }
        }
        __syncthreads();
#pragma unroll
        for (int kk = 0; kk < 16; kk++) {
            float ra[4], rb[4];
#pragma unroll
            for (int i = 0; i < 4; i++) ra[i] = As[kk][ty * 4 + i];
#pragma unroll
            for (int j = 0; j < 4; j++) rb[j] = Bs[kk][tx * 4 + j];
#pragma unroll
            for (int i = 0; i < 4; i++)
#pragma unroll
                for (int j = 0; j < 4; j++) acc[i][j] += ra[i] * rb[j];
        }
        __syncthreads();
    }

#pragma unroll
    for (int i = 0; i < 4; i++) {
        int gr = bm + ty * 4 + i;
        if (gr >= M) continue;
#pragma unroll
        for (int j = 0; j < 4; j++) {
            int gc = bn + tx * 4 + j;
            if (gc >= N) continue;
            float v = acc[i][j] * alpha;
            if (bias) v += bias[gc];
            if (ACT == ACT_SILU) v = v / (1.f + expf(-v));
            if (ACT == ACT_GELU) v = 0.5f * v * (1.f + erff(v * 0.70710678118654752f));
            long off = (long)gr * ldc + gc;
            if (ADD_C) v += (float)C[off];
            C[off] = (TC)v;
        }
    }
}

// ---------------- LayerNorm over fixed D=1024, block=256 -------------------------
template<typename Tin, typename Tout, bool AFFINE>
__global__ void __launch_bounds__(256) ln_k(const Tin* __restrict__ x, Tout* __restrict__ y,
                                            const float* __restrict__ g, const float* __restrict__ b)
{
    const long row = blockIdx.x;
    const Tin* xr = x + row * D_;
    const int t = threadIdx.x;
    float vals[4];
    float s = 0.f;
#pragma unroll
    for (int i = 0; i < 4; i++) { vals[i] = (float)xr[t + i * 256]; s += vals[i]; }
    __shared__ float red[256];
    red[t] = s; __syncthreads();
    for (int off = 128; off > 0; off >>= 1) { if (t < off) red[t] += red[t + off]; __syncthreads(); }
    float m = red[0] * (1.f / D_);
    __syncthreads();
    float vs = 0.f;
#pragma unroll
    for (int i = 0; i < 4; i++) { float d = vals[i] - m; vs += d * d; }
    red[t] = vs; __syncthreads();
    for (int off = 128; off > 0; off >>= 1) { if (t < off) red[t] += red[t + off]; __syncthreads(); }
    float var = red[0] * (1.f / D_);
    float rs = 1.f / sqrtf(var + 1e-5f);
#pragma unroll
    for (int i = 0; i < 4; i++) {
        int c = t + i * 256;
        float o = (vals[i] - m) * rs;
        if (AFFINE) o = o * g[c] + b[c];
        y[row * D_ + c] = (Tout)o;
    }
}

// ---------------- softmax over fixed 1024 cols -----------------------------------
__global__ void __launch_bounds__(256) softmax_k(float* __restrict__ x)
{
    const long row = blockIdx.x;
    float* p = x + row * N1_;
    const int t = threadIdx.x;
    float v[4]; float mx = -1e30f;
#pragma unroll
    for (int i = 0; i < 4; i++) { v[i] = p[t + i * 256]; mx = fmaxf(mx, v[i]); }
    __shared__ float red[256];
    red[t] = mx; __syncthreads();
    for (int off = 128; off > 0; off >>= 1) { if (t < off) red[t] = fmaxf(red[t], red[t + off]); __syncthreads(); }
    mx = red[0]; __syncthreads();
    float s = 0.f;
#pragma unroll
    for (int i = 0; i < 4; i++) { v[i] = expf(v[i] - mx); s += v[i]; }
    red[t] = s; __syncthreads();
    for (int off = 128; off > 0; off >>= 1) { if (t < off) red[t] += red[t + off]; __syncthreads(); }
    float inv = 1.f / red[0];
#pragma unroll
    for (int i = 0; i < 4; i++) p[t + i * 256] = v[i] * inv;
}

// ---------------- small elementwise kernels --------------------------------------
__global__ void timestep_k(const float* __restrict__ ts, float* __restrict__ out)
{
    int b = blockIdx.x, i = threadIdx.x;             // 320 threads
    int j = (i < 160) ? i : (i - 160);
    float f = expf(-logf(10000.f) * (float)j / 160.f);
    float af = ts[b] * f;                             // match reference fp32 angle
    double a = (double)af;
    out[b * TD_ + i] = (i < 160) ? (float)cos(a) : (float)sin(a);
}

__global__ void silu_k(const float* __restrict__ x, float* __restrict__ y, int n)
{
    int i = blockIdx.x * blockDim.x + threadIdx.x;
    if (i < n) { float v = x[i]; y[i] = v / (1.f + expf(-v)); }
}

__global__ void bcast_lat_k(const float* __restrict__ src, float* __restrict__ dst, int n, int period)
{
    int i = blockIdx.x * blockDim.x + threadIdx.x;
    if (i < n) dst[i] = src[i % period];
}

__global__ void modulate_k(float* __restrict__ q, const float* __restrict__ ada)
{
    int idx = blockIdx.x * blockDim.x + threadIdx.x;
    if (idx >= BS_ * NQ_ * D_) return;
    int b = idx / (NQ_ * D_);
    int c = idx & (D_ - 1);
    float sc = ada[b * 4 * D_ + 2 * D_ + c];
    float sh = ada[b * 4 * D_ + c];
    q[idx] = q[idx] * (1.f + sc) + sh;
}

__global__ void ovmod_k(float* __restrict__ ov, const float* __restrict__ g1, const float* __restrict__ b1)
{
    int idx = blockIdx.x * blockDim.x + threadIdx.x;
    if (idx >= BS_ * NQ_ * H_ * D_) return;
    int d = idx & (D_ - 1);
    ov[idx] = g1[d] * ov[idx] + b1[d];
}

// ---------------- launch ----------------------------------------------------------
static inline dim3 ggrid(int M, int N, int b)
{
    return dim3((unsigned)((N + 63) / 64), (unsigned)((M + 63) / 64), (unsigned)b);
}

extern "C" void kernel_launch(void* const* d_in, const int* in_sizes, int n_in,
                              void* d_out, int out_size)
{
    const float* in_x   = (const float*)d_in[0];
    const float* in_ts  = (const float*)d_in[1];
    const float* in_lat = (const float*)d_in[2];
    const float* te_w1  = (const float*)d_in[3];
    const float* te_b1  = (const float*)d_in[4];
    const float* te_w2  = (const float*)d_in[5];
    const float* te_b2  = (const float*)d_in[6];
    const float* pin_w  = (const float*)d_in[7];
    const float* pin_b  = (const float*)d_in[8];
    const float* ln1_g  = (const float*)d_in[9];
    const float* ln1_b  = (const float*)d_in[10];
    const float* ln2_g  = (const float*)d_in[11];
    const float* ln2_b  = (const float*)d_in[12];
    const float* wq     = (const float*)d_in[13];
    const float* wkv    = (const float*)d_in[14];
    const float* wo     = (const float*)d_in[15];
    const float* flg    = (const float*)d_in[16];
    const float* flb    = (const float*)d_in[17];
    const float* fw1    = (const float*)d_in[18];
    const float* fw2    = (const float*)d_in[19];
    const float* aw     = (const float*)d_in[20];
    const float* ab     = (const float*)d_in[21];
    const float* pout_w = (const float*)d_in[22];
    const float* pout_b = (const float*)d_in[23];
    const float* ng     = (const float*)d_in[24];
    const float* nb     = (const float*)d_in[25];
    float* out = (float*)d_out;

    float *xp, *temb0, *temb1, *temb, *stemb, *ada, *lat, *latn, *q, *qp, *att, *ov, *vout, *hff, *h1;
    __nv_bfloat16* xnorm;
    cudaGetSymbolAddress((void**)&xp,    g_xp);
    cudaGetSymbolAddress((void**)&xnorm, g_xnorm);
    cudaGetSymbolAddress((void**)&temb0, g_temb0);
    cudaGetSymbolAddress((void**)&temb1, g_temb1);
    cudaGetSymbolAddress((void**)&temb,  g_temb);
    cudaGetSymbolAddress((void**)&stemb, g_stemb);
    cudaGetSymbolAddress((void**)&ada,   g_ada);
    cudaGetSymbolAddress((void**)&lat,   g_lat);
    cudaGetSymbolAddress((void**)&latn,  g_latn);
    cudaGetSymbolAddress((void**)&q,     g_q);
    cudaGetSymbolAddress((void**)&qp,    g_qp);
    cudaGetSymbolAddress((void**)&att,   g_att);
    cudaGetSymbolAddress((void**)&ov,    g_ov);
    cudaGetSymbolAddress((void**)&vout,  g_vout);
    cudaGetSymbolAddress((void**)&hff,   g_hff);
    cudaGetSymbolAddress((void**)&h1,    g_h1);

    // --- timestep embedding: t_emb -> silu(linear) -> linear; stemb = silu(temb) ---
    timestep_k<<<BS_, TD_>>>(in_ts, temb0);
    gemm_k<float,float,float,ACT_SILU,false,false,false><<<ggrid(BS_, D_, 1), 256>>>(
        BS_, D_, TD_, temb0, TD_, 0, te_w1, D_, 0, temb1, D_, 0, te_b1, nullptr, 1.f);
    gemm_k<float,float,float,ACT_NONE,false,false,false><<<ggrid(BS_, D_, 1), 256>>>(
        BS_, D_, D_, temb1, D_, 0, te_w2, D_, 0, temb, D_, 0, te_b2, nullptr, 1.f);
    silu_k<<<(BS_*D_ + 255) / 256, 256>>>(temb, stemb, BS_ * D_);

    // --- proj_in + layer-invariant normalization of xp (bf16) ---
    gemm_k<float,float,float,ACT_NONE,false,false,false><<<ggrid(BS_*N1_, D_, 1), 256>>>(
        BS_*N1_, D_, ED_, in_x, ED_, 0, pin_w, D_, 0, xp, D_, 0, pin_b, nullptr, 1.f);
    ln_k<float,__nv_bfloat16,false><<<BS_*N1_, 256>>>(xp, xnorm, nullptr, nullptr);

    // --- broadcast latents ---
    bcast_lat_k<<<(BS_*NQ_*D_ + 255) / 256, 256>>>(in_lat, lat, BS_*NQ_*D_, NQ_*D_);

    for (int l = 0; l < DEPTH; l++) {
        const float* wq_l  = wq  + (long)l * D_ * INNER;
        const float* wkv_l = wkv + (long)l * D_ * 2 * INNER;
        const float* wo_l  = wo  + (long)l * INNER * D_;
        const float* fw1_l = fw1 + (long)l * D_ * FF_;
        const float* fw2_l = fw2 + (long)l * FF_ * D_;
        const float* aw_l  = aw  + (long)l * D_ * 4 * D_;
        const float* ab_l  = ab  + (long)l * 4 * D_;
        const float* g1 = ln1_g + l * D_;
        const float* b1 = ln1_b + l * D_;
        const float* g2 = ln2_g + l * D_;
        const float* b2 = ln2_b + l * D_;
        const float* fg = flg + l * D_;
        const float* fb = flb + l * D_;

        // adaLN params
        gemm_k<float,float,float,ACT_NONE,false,false,false><<<ggrid(BS_, 4*D_, 1), 256>>>(
            BS_, 4*D_, D_, stemb, D_, 0, aw_l, 4*D_, 0, ada, 4*D_, 0, ab_l, nullptr, 1.f);

        // latents LN + q projection + modulation
        ln_k<float,float,true><<<BS_*NQ_, 256>>>(lat, latn, g2, b2);
        gemm_k<float,float,float,ACT_NONE,false,false,false><<<ggrid(BS_*NQ_, INNER, 1), 256>>>(
            BS_*NQ_, INNER, D_, latn, D_, 0, wq_l, INNER, 0, q, INNER, 0, nullptr, nullptr, 1.f);
        modulate_k<<<(BS_*NQ_*D_ + 255) / 256, 256>>>(q, ada);

        // qproj[b,q,h,d] = SCALE * qmod[b,q,h,:] @ wk_h^T   (batched over heads, NT)
        gemm_k<float,float,float,ACT_NONE,false,false,true><<<ggrid(BS_*NQ_, D_, H_), 256>>>(
            BS_*NQ_, D_, DH_, q, INNER, 64, wkv_l, 2*INNER, 64,
            qp, H_*D_, (long)D_, nullptr, nullptr, SCALE_);

        // logits[b,(q,h),n] = (qproj .* g1) @ xnorm_b^T   (b1 term drops: softmax shift-invariant)
        gemm_k<float,__nv_bfloat16,float,ACT_NONE,false,true,true><<<ggrid(NQ_*H_, N1_, BS_), 256>>>(
            NQ_*H_, N1_, D_, qp, D_, (long)NQ_*H_*D_, xnorm, D_, (long)N1_*D_,
            att, N1_, (long)NQ_*H_*N1_, nullptr, g1, 1.f);

        softmax_k<<<BS_*NQ_*H_, 256>>>(att);

        // ov[b,(q,h),d] = attn @ xnorm_b
        gemm_k<float,__nv_bfloat16,float,ACT_NONE,false,false,false><<<ggrid(NQ_*H_, D_, BS_), 256>>>(
            NQ_*H_, D_, N1_, att, N1_, (long)NQ_*H_*N1_, xnorm, D_, (long)N1_*D_,
            ov, D_, (long)NQ_*H_*D_, nullptr, nullptr, 1.f);

        // ov <- g1*ov + b1  (b1 survives since sum(attn)=1)
        ovmod_k<<<(BS_*NQ_*H_*D_ + 255) / 256, 256>>>(ov, g1, b1);

        // vout[b,q,h*64+dh] = ovm[b,q,h,:] @ wv_h   (batched over heads, NN)
        gemm_k<float,float,float,ACT_NONE,false,false,false><<<ggrid(BS_*NQ_, DH_, H_), 256>>>(
            BS_*NQ_, DH_, D_, ov, H_*D_, (long)D_, wkv_l + INNER, 2*INNER, 64,
            vout, D_, 64, nullptr, nullptr, 1.f);

        // lat += vout @ wo
        gemm_k<float,float,float,ACT_NONE,true,false,false><<<ggrid(BS_*NQ_, D_, 1), 256>>>(
            BS_*NQ_, D_, INNER, vout, INNER, 0, wo_l, D_, 0, lat, D_, 0, nullptr, nullptr, 1.f);

        // FF block
        ln_k<float,float,true><<<BS_*NQ_, 256>>>(lat, hff, fg, fb);
        gemm_k<float,float,float,ACT_GELU,false,false,false><<<ggrid(BS_*NQ_, FF_, 1), 256>>>(
            BS_*NQ_, FF_, D_, hff, D_, 0, fw1_l, FF_, 0, h1, FF_, 0, nullptr, nullptr, 1.f);
        gemm_k<float,float,float,ACT_NONE,true,false,false><<<ggrid(BS_*NQ_, D_, 1), 256>>>(
            BS_*NQ_, D_, FF_, h1, FF_, 0, fw2_l, D_, 0, lat, D_, 0, nullptr, nullptr, 1.f);
    }

    // --- proj_out + final LN ---
    gemm_k<float,float,float,ACT_NONE,false,false,false><<<ggrid(BS_*NQ_, D_, 1), 256>>>(
        BS_*NQ_, D_, D_, lat, D_, 0, pout_w, D_, 0, hff, D_, 0, pout_b, nullptr, 1.f);
    ln_k<float,float,true><<<BS_*NQ_, 256>>>(hff, out, ng, nb);
}

// round 2
// speedup vs baseline: 1.0006x; 1.0006x over previous
#include <cuda_runtime.h>
#include <cuda_bf16.h>
#include <math.h>

#define D_    1024
#define DEPTH 8
#define H_    16
#define DH_   64
#define INNER 1024
#define NQ_   8
#define ED_   768
#define FF_   4096
#define TD_   320
#define BS_   32
#define N1_   1024
#define SCALE_ 0.125f

#define ACT_NONE 0
#define ACT_SILU 1
#define ACT_GELU 2

// ---------------- static scratch (no runtime allocation allowed) ----------------
__device__ float         g_xp[BS_*N1_*D_];          // 134 MB
__device__ __nv_bfloat16 g_xnorm[BS_*N1_*D_];       // 67 MB
__device__ float g_temb0[BS_*TD_];
__device__ float g_temb1[BS_*D_];
__device__ float g_temb [BS_*D_];
__device__ float g_stemb[BS_*D_];
__device__ float g_ada  [BS_*4*D_];
__device__ float g_lat  [BS_*NQ_*D_];
__device__ float g_latn [BS_*NQ_*D_];
__device__ float g_q    [BS_*NQ_*D_];
__device__ float g_qp   [BS_*NQ_*H_*D_];            // (b,q,h,d) 16.8 MB
__device__ float g_att  [BS_*NQ_*H_*N1_];           // logits -> attn, 16.8 MB
__device__ float g_ov   [BS_*NQ_*H_*D_];            // 16.8 MB
__device__ float g_vout [BS_*NQ_*D_];
__device__ float g_hff  [BS_*NQ_*D_];
__device__ float g_h1   [BS_*NQ_*FF_];

// ---------------- generic tiled SGEMM: C = act(alpha*A(.ascale)@B(/Bt) + bias) [+C] ----
// BM=BN=64, BK=16, 256 threads, 4x4 per thread. K must be a multiple of 16 (true here).
template<typename TA, typename TB, typename TC, int ACT, bool ADD_C, bool ASCALE, bool BT>
__global__ void __launch_bounds__(256) gemm_k(
    int M, int N, int K,
    const TA* __restrict__ A, int lda, long sA,
    const TB* __restrict__ B, int ldb, long sB,
    TC* __restrict__ C, int ldc, long sC,
    const float* __restrict__ bias,
    const float* __restrict__ ascale,
    float alpha)
{
    __shared__ float As[16][68];
    __shared__ float Bs[16][68];
    A += (long)blockIdx.z * sA;
    B += (long)blockIdx.z * sB;
    C += (long)blockIdx.z * sC;
    const int bm = blockIdx.y * 64;
    const int bn = blockIdx.x * 64;
    const int tid = threadIdx.x;
    const int tx = tid & 15, ty = tid >> 4;

    float acc[4][4];
#pragma unroll
    for (int i = 0; i < 4; i++)
#pragma unroll
        for (int j = 0; j < 4; j++) acc[i][j] = 0.f;

    for (int k0 = 0; k0 < K; k0 += 16) {
#pragma unroll
        for (int i = 0; i < 4; i++) {
            int idx = tid + i * 256;
            int r = idx >> 4, kk = idx & 15;
            float v = 0.f;
            int gr = bm + r;
            if (gr < M) v = (float)A[(long)gr * lda + (k0 + kk)];
            if (ASCALE) v *= ascale[k0 + kk];
            As[kk][r] = v;
        }
#pragma unroll
        for (int i = 0; i < 4; i++) {
            int idx = tid + i * 256;
            if (!BT) {
                int kk = idx >> 6, c = idx & 63;
                int gc = bn + c;
                float v = 0.f;
                if (gc < N) v = (float)B[(long)(k0 + kk) * ldb + gc];
                Bs[kk][c] = v;
            } else {
                int c = idx >> 4, kk = idx & 15;
                int gc = bn + c;
                float v = 0.f;
                if (gc < N) v = (float)B[(long)gc * ldb + (k0 + kk)];
                Bs[kk][c] = v;
            }
        }
        __syncthreads();
#pragma unroll
        for (int kk = 0; kk < 16; kk++) {
            float ra[4], rb[4];
#pragma unroll
            for (int i = 0; i < 4; i++) ra[i] = As[kk][ty * 4 + i];
#pragma unroll
            for (int j = 0; j < 4; j++) rb[j] = Bs[kk][tx * 4 + j];
#pragma unroll
            for (int i = 0; i < 4; i++)
#pragma unroll
                for (int j = 0; j < 4; j++) acc[i][j] += ra[i] * rb[j];
        }
        __syncthreads();
    }

#pragma unroll
    for (int i = 0; i < 4; i++) {
        int gr = bm + ty * 4 + i;
        if (gr >= M) continue;
#pragma unroll
        for (int j = 0; j < 4; j++) {
            int gc = bn + tx * 4 + j;
            if (gc >= N) continue;
            float v = acc[i][j] * alpha;
            if (bias) v += bias[gc];
            if (ACT == ACT_SILU) v = v / (1.f + expf(-v));
            if (ACT == ACT_GELU) v = 0.5f * v * (1.f + erff(v * 0.70710678118654752f));
            long off = (long)gr * ldc + gc;
            if (ADD_C) v += (float)C[off];
            C[off] = (TC)v;
        }
    }
}

// ---------------- LayerNorm over fixed D=1024, block=256 -------------------------
template<typename Tin, typename Tout, bool AFFINE>
__global__ void __launch_bounds__(256) ln_k(const Tin* __restrict__ x, Tout* __restrict__ y,
                                            const float* __restrict__ g, const float* __restrict__ b)
{
    const long row = blockIdx.x;
    const Tin* xr = x + row * D_;
    const int t = threadIdx.x;
    float vals[4];
    float s = 0.f;
#pragma unroll
    for (int i = 0; i < 4; i++) { vals[i] = (float)xr[t + i * 256]; s += vals[i]; }
    __shared__ float red[256];
    red[t] = s; __syncthreads();
    for (int off = 128; off > 0; off >>= 1) { if (t < off) red[t] += red[t + off]; __syncthreads(); }
    float m = red[0] * (1.f / D_);
    __syncthreads();
    float vs = 0.f;
#pragma unroll
    for (int i = 0; i < 4; i++) { float d = vals[i] - m; vs += d * d; }
    red[t] = vs; __syncthreads();
    for (int off = 128; off > 0; off >>= 1) { if (t < off) red[t] += red[t + off]; __syncthreads(); }
    float var = red[0] * (1.f / D_);
    float rs = 1.f / sqrtf(var + 1e-5f);
#pragma unroll
    for (int i = 0; i < 4; i++) {
        int c = t + i * 256;
        float o = (vals[i] - m) * rs;
        if (AFFINE) o = o * g[c] + b[c];
        y[row * D_ + c] = (Tout)o;
    }
}

// ---------------- softmax over fixed 1024 cols -----------------------------------
__global__ void __launch_bounds__(256) softmax_k(float* __restrict__ x)
{
    const long row = blockIdx.x;
    float* p = x + row * N1_;
    const int t = threadIdx.x;
    float v[4]; float mx = -1e30f;
#pragma unroll
    for (int i = 0; i < 4; i++) { v[i] = p[t + i * 256]; mx = fmaxf(mx, v[i]); }
    __shared__ float red[256];
    red[t] = mx; __syncthreads();
    for (int off = 128; off > 0; off >>= 1) { if (t < off) red[t] = fmaxf(red[t], red[t + off]); __syncthreads(); }
    mx = red[0]; __syncthreads();
    float s = 0.f;
#pragma unroll
    for (int i = 0; i < 4; i++) { v[i] = expf(v[i] - mx); s += v[i]; }
    red[t] = s; __syncthreads();
    for (int off = 128; off > 0; off >>= 1) { if (t < off) red[t] += red[t + off]; __syncthreads(); }
    float inv = 1.f / red[0];
#pragma unroll
    for (int i = 0; i < 4; i++) p[t + i * 256] = v[i] * inv;
}

// ---------------- small elementwise kernels --------------------------------------
__global__ void timestep_k(const float* __restrict__ ts, float* __restrict__ out)
{
    int b = blockIdx.x, i = threadIdx.x;             // 320 threads
    int j = (i < 160) ? i : (i - 160);
    float f = expf(-logf(10000.f) * (float)j / 160.f);
    float af = ts[b] * f;                             // match reference fp32 angle
    double a = (double)af;
    out[b * TD_ + i] = (i < 160) ? (float)cos(a) : (float)sin(a);
}

__global__ void silu_k(const float* __restrict__ x, float* __restrict__ y, int n)
{
    int i = blockIdx.x * blockDim.x + threadIdx.x;
    if (i < n) { float v = x[i]; y[i] = v / (1.f + expf(-v)); }
}

__global__ void bcast_lat_k(const float* __restrict__ src, float* __restrict__ dst, int n, int period)
{
    int i = blockIdx.x * blockDim.x + threadIdx.x;
    if (i < n) dst[i] = src[i % period];
}

__global__ void modulate_k(float* __restrict__ q, const float* __restrict__ ada)
{
    int idx = blockIdx.x * blockDim.x + threadIdx.x;
    if (idx >= BS_ * NQ_ * D_) return;
    int b = idx / (NQ_ * D_);
    int c = idx & (D_ - 1);
    float sc = ada[b * 4 * D_ + 2 * D_ + c];
    float sh = ada[b * 4 * D_ + c];
    q[idx] = q[idx] * (1.f + sc) + sh;
}

__global__ void ovmod_k(float* __restrict__ ov, const float* __restrict__ g1, const float* __restrict__ b1)
{
    int idx = blockIdx.x * blockDim.x + threadIdx.x;
    if (idx >= BS_ * NQ_ * H_ * D_) return;
    int d = idx & (D_ - 1);
    ov[idx] = g1[d] * ov[idx] + b1[d];
}

// ---------------- launch ----------------------------------------------------------
static inline dim3 ggrid(int M, int N, int b)
{
    return dim3((unsigned)((N + 63) / 64), (unsigned)((M + 63) / 64), (unsigned)b);
}

extern "C" void kernel_launch(void* const* d_in, const int* in_sizes, int n_in,
                              void* d_out, int out_size)
{
    const float* in_x   = (const float*)d_in[0];
    const float* in_ts  = (const float*)d_in[1];
    const float* in_lat = (const float*)d_in[2];
    const float* te_w1  = (const float*)d_in[3];
    const float* te_b1  = (const float*)d_in[4];
    const float* te_w2  = (const float*)d_in[5];
    const float* te_b2  = (const float*)d_in[6];
    const float* pin_w  = (const float*)d_in[7];
    const float* pin_b  = (const float*)d_in[8];
    const float* ln1_g  = (const float*)d_in[9];
    const float* ln1_b  = (const float*)d_in[10];
    const float* ln2_g  = (const float*)d_in[11];
    const float* ln2_b  = (const float*)d_in[12];
    const float* wq     = (const float*)d_in[13];
    const float* wkv    = (const float*)d_in[14];
    const float* wo     = (const float*)d_in[15];
    const float* flg    = (const float*)d_in[16];
    const float* flb    = (const float*)d_in[17];
    const float* fw1    = (const float*)d_in[18];
    const float* fw2    = (const float*)d_in[19];
    const float* aw     = (const float*)d_in[20];
    const float* ab     = (const float*)d_in[21];
    const float* pout_w = (const float*)d_in[22];
    const float* pout_b = (const float*)d_in[23];
    const float* ng     = (const float*)d_in[24];
    const float* nb     = (const float*)d_in[25];
    float* out = (float*)d_out;

    float *xp, *temb0, *temb1, *temb, *stemb, *ada, *lat, *latn, *q, *qp, *att, *ov, *vout, *hff, *h1;
    __nv_bfloat16* xnorm;
    cudaGetSymbolAddress((void**)&xp,    g_xp);
    cudaGetSymbolAddress((void**)&xnorm, g_xnorm);
    cudaGetSymbolAddress((void**)&temb0, g_temb0);
    cudaGetSymbolAddress((void**)&temb1, g_temb1);
    cudaGetSymbolAddress((void**)&temb,  g_temb);
    cudaGetSymbolAddress((void**)&stemb, g_stemb);
    cudaGetSymbolAddress((void**)&ada,   g_ada);
    cudaGetSymbolAddress((void**)&lat,   g_lat);
    cudaGetSymbolAddress((void**)&latn,  g_latn);
    cudaGetSymbolAddress((void**)&q,     g_q);
    cudaGetSymbolAddress((void**)&qp,    g_qp);
    cudaGetSymbolAddress((void**)&att,   g_att);
    cudaGetSymbolAddress((void**)&ov,    g_ov);
    cudaGetSymbolAddress((void**)&vout,  g_vout);
    cudaGetSymbolAddress((void**)&hff,   g_hff);
    cudaGetSymbolAddress((void**)&h1,    g_h1);

    // --- timestep embedding: t_emb -> silu(linear) -> linear; stemb = silu(temb) ---
    timestep_k<<<BS_, TD_>>>(in_ts, temb0);
    gemm_k<float,float,float,ACT_SILU,false,false,false><<<ggrid(BS_, D_, 1), 256>>>(
        BS_, D_, TD_, temb0, TD_, 0, te_w1, D_, 0, temb1, D_, 0, te_b1, nullptr, 1.f);
    gemm_k<float,float,float,ACT_NONE,false,false,false><<<ggrid(BS_, D_, 1), 256>>>(
        BS_, D_, D_, temb1, D_, 0, te_w2, D_, 0, temb, D_, 0, te_b2, nullptr, 1.f);
    silu_k<<<(BS_*D_ + 255) / 256, 256>>>(temb, stemb, BS_ * D_);

    // --- proj_in + layer-invariant normalization of xp (bf16) ---
    gemm_k<float,float,float,ACT_NONE,false,false,false><<<ggrid(BS_*N1_, D_, 1), 256>>>(
        BS_*N1_, D_, ED_, in_x, ED_, 0, pin_w, D_, 0, xp, D_, 0, pin_b, nullptr, 1.f);
    ln_k<float,__nv_bfloat16,false><<<BS_*N1_, 256>>>(xp, xnorm, nullptr, nullptr);

    // --- broadcast latents ---
    bcast_lat_k<<<(BS_*NQ_*D_ + 255) / 256, 256>>>(in_lat, lat, BS_*NQ_*D_, NQ_*D_);

    for (int l = 0; l < DEPTH; l++) {
        const float* wq_l  = wq  + (long)l * D_ * INNER;
        const float* wkv_l = wkv + (long)l * D_ * 2 * INNER;
        const float* wo_l  = wo  + (long)l * INNER * D_;
        const float* fw1_l = fw1 + (long)l * D_ * FF_;
        const float* fw2_l = fw2 + (long)l * FF_ * D_;
        const float* aw_l  = aw  + (long)l * D_ * 4 * D_;
        const float* ab_l  = ab  + (long)l * 4 * D_;
        const float* g1 = ln1_g + l * D_;
        const float* b1 = ln1_b + l * D_;
        const float* g2 = ln2_g + l * D_;
        const float* b2 = ln2_b + l * D_;
        const float* fg = flg + l * D_;
        const float* fb = flb + l * D_;

        // adaLN params
        gemm_k<float,float,float,ACT_NONE,false,false,false><<<ggrid(BS_, 4*D_, 1), 256>>>(
            BS_, 4*D_, D_, stemb, D_, 0, aw_l, 4*D_, 0, ada, 4*D_, 0, ab_l, nullptr, 1.f);

        // latents LN + q projection + modulation
        ln_k<float,float,true><<<BS_*NQ_, 256>>>(lat, latn, g2, b2);
        gemm_k<float,float,float,ACT_NONE,false,false,false><<<ggrid(BS_*NQ_, INNER, 1), 256>>>(
            BS_*NQ_, INNER, D_, latn, D_, 0, wq_l, INNER, 0, q, INNER, 0, nullptr, nullptr, 1.f);
        modulate_k<<<(BS_*NQ_*D_ + 255) / 256, 256>>>(q, ada);

        // qproj[b,q,h,d] = SCALE * qmod[b,q,h,:] @ wk_h^T   (batched over heads, NT)
        gemm_k<float,float,float,ACT_NONE,false,false,true><<<ggrid(BS_*NQ_, D_, H_), 256>>>(
            BS_*NQ_, D_, DH_, q, INNER, 64, wkv_l, 2*INNER, 64,
            qp, H_*D_, (long)D_, nullptr, nullptr, SCALE_);

        // logits[b,(q,h),n] = (qproj .* g1) @ xnorm_b^T   (b1 term drops: softmax shift-invariant)
        gemm_k<float,__nv_bfloat16,float,ACT_NONE,false,true,true><<<ggrid(NQ_*H_, N1_, BS_), 256>>>(
            NQ_*H_, N1_, D_, qp, D_, (long)NQ_*H_*D_, xnorm, D_, (long)N1_*D_,
            att, N1_, (long)NQ_*H_*N1_, nullptr, g1, 1.f);

        softmax_k<<<BS_*NQ_*H_, 256>>>(att);

        // ov[b,(q,h),d] = attn @ xnorm_b
        gemm_k<float,__nv_bfloat16,float,ACT_NONE,false,false,false><<<ggrid(NQ_*H_, D_, BS_), 256>>>(
            NQ_*H_, D_, N1_, att, N1_, (long)NQ_*H_*N1_, xnorm, D_, (long)N1_*D_,
            ov, D_, (long)NQ_*H_*D_, nullptr, nullptr, 1.f);

        // ov <- g1*ov + b1  (b1 survives since sum(attn)=1)
        ovmod_k<<<(BS_*NQ_*H_*D_ + 255) / 256, 256>>>(ov, g1, b1);

        // vout[b,q,h*64+dh] = ovm[b,q,h,:] @ wv_h   (batched over heads, NN)
        gemm_k<float,float,float,ACT_NONE,false,false,false><<<ggrid(BS_*NQ_, DH_, H_), 256>>>(
            BS_*NQ_, DH_, D_, ov, H_*D_, (long)D_, wkv_l + INNER, 2*INNER, 64,
            vout, D_, 64, nullptr, nullptr, 1.f);

        // lat += vout @ wo
        gemm_k<float,float,float,ACT_NONE,true,false,false><<<ggrid(BS_*NQ_, D_, 1), 256>>>(
            BS_*NQ_, D_, INNER, vout, INNER, 0, wo_l, D_, 0, lat, D_, 0, nullptr, nullptr, 1.f);

        // FF block
        ln_k<float,float,true><<<BS_*NQ_, 256>>>(lat, hff, fg, fb);
        gemm_k<float,float,float,ACT_GELU,false,false,false><<<ggrid(BS_*NQ_, FF_, 1), 256>>>(
            BS_*NQ_, FF_, D_, hff, D_, 0, fw1_l, FF_, 0, h1, FF_, 0, nullptr, nullptr, 1.f);
        gemm_k<float,float,float,ACT_NONE,true,false,false><<<ggrid(BS_*NQ_, D_, 1), 256>>>(
            BS_*NQ_, D_, FF_, h1, FF_, 0, fw2_l, D_, 0, lat, D_, 0, nullptr, nullptr, 1.f);
    }

    // --- proj_out + final LN ---
    gemm_k<float,float,float,ACT_NONE,false,false,false><<<ggrid(BS_*NQ_, D_, 1), 256>>>(
        BS_*NQ_, D_, D_, lat, D_, 0, pout_w, D_, 0, hff, D_, 0, pout_b, nullptr, 1.f);
    ln_k<float,float,true><<<BS_*NQ_, 256>>>(hff, out, ng, nb);
}